// round 2
// baseline (speedup 1.0000x reference)
#include <cuda_runtime.h>
#include <math.h>

#define S_DIM 128
#define R_DIM 256
#define CS 256
#define CH 32
#define CZ 128
#define MDIM 8192           // R_DIM * CH
#define NROWS 32768         // S_DIM * R_DIM
#define LN_EPS 1e-5f
#define MASK_EPS 1e-3f

// Scratch (static __device__ arrays — no cudaMalloc allowed)
__device__ float g_a[S_DIM * MDIM];                 // [s][i*32+h], 4 MB
__device__ float g_b[S_DIM * MDIM];                 // [s][j*32+k], 4 MB
__device__ float g_outer[(size_t)65536 * 1024];     // [i][j][h][k], 268 MB

// ---- packed fp32 (f32x2) helpers: SASS FFMA2 path, 2x fp32 throughput -----
__device__ __forceinline__ unsigned long long pack2(float x, float y) {
    unsigned long long r;
    asm("mov.b64 %0, {%1, %2};" : "=l"(r) : "f"(x), "f"(y));
    return r;
}
__device__ __forceinline__ void unpack2(unsigned long long v, float& x, float& y) {
    asm("mov.b64 {%0, %1}, %2;" : "=f"(x), "=f"(y) : "l"(v));
}
__device__ __forceinline__ unsigned long long ffma2(
    unsigned long long a, unsigned long long b, unsigned long long c) {
    unsigned long long d;
    asm("fma.rn.f32x2 %0, %1, %2, %3;" : "=l"(d) : "l"(a), "l"(b), "l"(c));
    return d;
}

// ---------------------------------------------------------------------------
// Kernel 1: LayerNorm + dual projection (+bias, *mask) -> g_a, g_b
// ---------------------------------------------------------------------------
__global__ __launch_bounds__(256) void k_proj(
    const float* __restrict__ m, const float* __restrict__ mask,
    const float* __restrict__ lnw, const float* __restrict__ lnb,
    const float* __restrict__ w1, const float* __restrict__ b1,
    const float* __restrict__ w2, const float* __restrict__ b2)
{
    __shared__ float mhs[16][CS];
    __shared__ float lnws[CS], lnbs[CS];

    int tid  = threadIdx.x;
    int lane = tid & 31;
    int wid  = tid >> 5;

    lnws[tid] = lnw[tid];
    lnbs[tid] = lnb[tid];
    __syncthreads();

    int row0 = blockIdx.x * 16;

    #pragma unroll
    for (int rr = 0; rr < 2; rr++) {
        int rl  = wid * 2 + rr;
        int row = row0 + rl;
        const float4* mrow = (const float4*)(m + (size_t)row * CS);
        float4 v0 = mrow[lane * 2];
        float4 v1 = mrow[lane * 2 + 1];
        float s1 = v0.x + v0.y + v0.z + v0.w + v1.x + v1.y + v1.z + v1.w;
        float s2 = v0.x*v0.x + v0.y*v0.y + v0.z*v0.z + v0.w*v0.w
                 + v1.x*v1.x + v1.y*v1.y + v1.z*v1.z + v1.w*v1.w;
        #pragma unroll
        for (int off = 16; off; off >>= 1) {
            s1 += __shfl_xor_sync(0xffffffffu, s1, off);
            s2 += __shfl_xor_sync(0xffffffffu, s2, off);
        }
        float mu   = s1 * (1.0f / CS);
        float var  = s2 * (1.0f / CS) - mu * mu;
        float rstd = rsqrtf(var + LN_EPS);
        int c0 = lane * 8;
        float t[8] = {v0.x, v0.y, v0.z, v0.w, v1.x, v1.y, v1.z, v1.w};
        #pragma unroll
        for (int q = 0; q < 8; q++) {
            int c = c0 + q;
            mhs[rl][c] = (t[q] - mu) * rstd * lnws[c] + lnbs[c];
        }
    }
    __syncthreads();

    int o  = tid & 63;
    int rg = tid >> 6;
    int h  = o & 31;
    const float* wp = (o < 32) ? (w1 + h) : (w2 + h);
    float acc0 = 0.f, acc1 = 0.f, acc2 = 0.f, acc3 = 0.f;
    #pragma unroll 8
    for (int c = 0; c < CS; c++) {
        float wv = __ldg(wp + c * CH);
        acc0 += mhs[rg * 4 + 0][c] * wv;
        acc1 += mhs[rg * 4 + 1][c] * wv;
        acc2 += mhs[rg * 4 + 2][c] * wv;
        acc3 += mhs[rg * 4 + 3][c] * wv;
    }
    float bias = (o < 32) ? b1[h] : b2[h];
    float* dst = (o < 32) ? g_a : g_b;
    float accs[4] = {acc0, acc1, acc2, acc3};
    #pragma unroll
    for (int jj = 0; jj < 4; jj++) {
        int row = row0 + rg * 4 + jj;
        int s = row >> 8;
        int r = row & 255;
        float val = (accs[jj] + bias) * mask[row];
        dst[(size_t)s * MDIM + r * CH + h] = val;
    }
}

// ---------------------------------------------------------------------------
// Kernel 2: outer contraction GEMM with FFMA2 swap-pair trick.
// C[m=(i,h), n=(j,k)] = sum_s A[s,m]*B[s,n]
// 128x128 tile; per thread 8x8 outputs as 4x4 pair-blocks, each pair-block
// = 2 FFMA2 (diag with Bs, cross with element-swapped Bsw). No packing MOVs.
// ---------------------------------------------------------------------------
__global__ __launch_bounds__(256) void k_gemm1()
{
    __shared__ float As[32 * 128];    // [k][m]
    __shared__ float Bs[32 * 128];    // [k][n]
    __shared__ float Bsw[32 * 128];   // [k][n^1] (adjacent-swapped)

    int tid = threadIdx.x;
    int m0 = blockIdx.x * 128;
    int n0 = blockIdx.y * 128;
    int tx = tid & 15;
    int ty = tid >> 4;

    unsigned long long accd[4][4], accx[4][4];
    #pragma unroll
    for (int a = 0; a < 4; a++)
        #pragma unroll
        for (int b = 0; b < 4; b++) { accd[a][b] = 0ULL; accx[a][b] = 0ULL; }

    for (int k0 = 0; k0 < S_DIM; k0 += 32) {
        if (k0) __syncthreads();
        #pragma unroll
        for (int i4 = 0; i4 < 4; i4++) {
            int f4 = tid + i4 * 256;
            int k  = f4 >> 5;
            int q  = f4 & 31;
            float4 va = *(const float4*)&g_a[(size_t)(k0 + k) * MDIM + m0 + q * 4];
            float4 vb = *(const float4*)&g_b[(size_t)(k0 + k) * MDIM + n0 + q * 4];
            *(float4*)&As[k * 128 + q * 4]  = va;
            *(float4*)&Bs[k * 128 + q * 4]  = vb;
            *(float4*)&Bsw[k * 128 + q * 4] = make_float4(vb.y, vb.x, vb.w, vb.z);
        }
        __syncthreads();

        #pragma unroll 8
        for (int k = 0; k < 32; k++) {
            ulonglong2 A0 = *(const ulonglong2*)&As[k * 128 + tx * 4];
            ulonglong2 A1 = *(const ulonglong2*)&As[k * 128 + 64 + tx * 4];
            ulonglong2 B0 = *(const ulonglong2*)&Bs[k * 128 + ty * 4];
            ulonglong2 B1 = *(const ulonglong2*)&Bs[k * 128 + 64 + ty * 4];
            ulonglong2 W0 = *(const ulonglong2*)&Bsw[k * 128 + ty * 4];
            ulonglong2 W1 = *(const ulonglong2*)&Bsw[k * 128 + 64 + ty * 4];
            unsigned long long am[4] = {A0.x, A0.y, A1.x, A1.y};
            unsigned long long bn[4] = {B0.x, B0.y, B1.x, B1.y};
            unsigned long long bw[4] = {W0.x, W0.y, W1.x, W1.y};
            #pragma unroll
            for (int mp = 0; mp < 4; mp++)
                #pragma unroll
                for (int np = 0; np < 4; np++) {
                    accd[mp][np] = ffma2(am[mp], bn[np], accd[mp][np]);
                    accx[mp][np] = ffma2(am[mp], bw[np], accx[mp][np]);
                }
        }
    }

    // Epilogue. am pair mp covers rows m_even, m_even+1; bn pair np covers
    // n_even, n_even+1. d=(ae*be, ao*bo), x=(ae*bo, ao*be).
    #pragma unroll
    for (int mp = 0; mp < 4; mp++) {
        int m_even = m0 + ((mp >= 2) ? 64 : 0) + tx * 4 + (mp & 1) * 2;
        int i0 = m_even >> 5;
        int h0 = m_even & 31;          // even row
        int h1 = h0 + 1;               // odd row (same i: tx*4+? never crosses 32? m_even&31 -> h0<=30 within pair ✓)
        #pragma unroll
        for (int half = 0; half < 2; half++) {
            int np0 = half * 2;
            int nb = n0 + half * 64 + ty * 4;   // 4 consecutive n
            int j  = nb >> 5;
            int kk = nb & 31;
            float d0l, d0h, x0l, x0h, d1l, d1h, x1l, x1h;
            unpack2(accd[mp][np0],     d0l, d0h);
            unpack2(accx[mp][np0],     x0l, x0h);
            unpack2(accd[mp][np0 + 1], d1l, d1h);
            unpack2(accx[mp][np0 + 1], x1l, x1h);
            size_t base = (size_t)(i0 * R_DIM + j) * 1024 + kk;
            *(float4*)&g_outer[base + (size_t)h0 * 32] = make_float4(d0l, x0l, d1l, x1l);
            *(float4*)&g_outer[base + (size_t)h1 * 32] = make_float4(x0h, d0h, x1h, d1h);
        }
    }
}

// ---------------------------------------------------------------------------
// Kernel 3: output GEMM + bias + mask-norm divide, FFMA2 with packed W pairs
// and broadcast-A replicated via mov.b64 (ALU pipe, hidden under fma pipe).
// ---------------------------------------------------------------------------
__global__ __launch_bounds__(256) void k_gemm2(
    const float* __restrict__ mask, const float* __restrict__ w_out,
    const float* __restrict__ b_out, float* __restrict__ out)
{
    __shared__ float Ws[32 * 128];   // [kk][z]
    __shared__ float Asm[64 * 32];   // [p][kk]
    __shared__ float norms[64];

    int tid = threadIdx.x;
    int p0  = blockIdx.x * 64;
    int i   = p0 >> 8;
    int j0  = p0 & 255;

    if (tid < 64) {
        float nacc = 0.f;
        #pragma unroll 4
        for (int s = 0; s < S_DIM; s++)
            nacc += mask[s * R_DIM + i] * mask[s * R_DIM + j0 + tid];
        norms[tid] = nacc;
    }

    int tz = tid & 31;     // z quad: z0 = tz*4
    int tp = tid >> 5;     // 8 p-groups of 8 pairs each

    unsigned long long acc2[8][2];
    #pragma unroll
    for (int a = 0; a < 8; a++) { acc2[a][0] = 0ULL; acc2[a][1] = 0ULL; }

    for (int kk0 = 0; kk0 < 1024; kk0 += 32) {
        __syncthreads();
        #pragma unroll
        for (int i4 = 0; i4 < 2; i4++) {
            int f4 = tid + i4 * 256;
            int pp = f4 >> 3;
            int kq = f4 & 7;
            *(float4*)&Asm[pp * 32 + kq * 4] =
                *(const float4*)&g_outer[(size_t)(p0 + pp) * 1024 + kk0 + kq * 4];
        }
        #pragma unroll
        for (int i4 = 0; i4 < 4; i4++) {
            int f4 = tid + i4 * 256;
            int kk = f4 >> 5;
            int zq = f4 & 31;
            *(float4*)&Ws[kk * 128 + zq * 4] =
                *(const float4*)&w_out[(size_t)(kk0 + kk) * 128 + zq * 4];
        }
        __syncthreads();

        #pragma unroll 8
        for (int kk = 0; kk < 32; kk++) {
            ulonglong2 w01 = *(const ulonglong2*)&Ws[kk * 128 + tz * 4];
            #pragma unroll
            for (int jj = 0; jj < 8; jj++) {
                float av = Asm[(tp * 8 + jj) * 32 + kk];
                unsigned long long av2 = pack2(av, av);
                acc2[jj][0] = ffma2(av2, w01.x, acc2[jj][0]);
                acc2[jj][1] = ffma2(av2, w01.y, acc2[jj][1]);
            }
        }
    }

    float4 bz = *(const float4*)&b_out[tz * 4];
    #pragma unroll
    for (int jj = 0; jj < 8; jj++) {
        int pp = tp * 8 + jj;
        float inv = 1.0f / (MASK_EPS + norms[pp]);
        float a0, a1, a2, a3;
        unpack2(acc2[jj][0], a0, a1);
        unpack2(acc2[jj][1], a2, a3);
        float4 v = make_float4((a0 + bz.x) * inv, (a1 + bz.y) * inv,
                               (a2 + bz.z) * inv, (a3 + bz.w) * inv);
        *(float4*)&out[(size_t)(p0 + pp) * CZ + tz * 4] = v;
    }
}

// ---------------------------------------------------------------------------
extern "C" void kernel_launch(void* const* d_in, const int* in_sizes, int n_in,
                              void* d_out, int out_size)
{
    const float* m     = (const float*)d_in[0];
    const float* mask  = (const float*)d_in[1];
    const float* lnw   = (const float*)d_in[2];
    const float* lnb   = (const float*)d_in[3];
    const float* w1    = (const float*)d_in[4];
    const float* b1    = (const float*)d_in[5];
    const float* w2    = (const float*)d_in[6];
    const float* b2    = (const float*)d_in[7];
    const float* w_out = (const float*)d_in[8];
    const float* b_out = (const float*)d_in[9];
    float* out = (float*)d_out;

    k_proj<<<NROWS / 16, 256>>>(m, mask, lnw, lnb, w1, b1, w2, b2);
    k_gemm1<<<dim3(MDIM / 128, MDIM / 128), 256>>>();
    k_gemm2<<<(R_DIM * R_DIM) / 64, 256>>>(mask, w_out, b_out, out);
}

// round 4
// speedup vs baseline: 1.4397x; 1.4397x over previous
#include <cuda_runtime.h>
#include <cuda_bf16.h>
#include <math.h>
#include <cstdint>

#define S_DIM 128
#define R_DIM 256
#define CS 256
#define CH 32
#define CZ 128
#define MDIM 8192           // R_DIM * CH
#define LN_EPS 1e-5f
#define MASK_EPS 1e-3f

// Scratch (static __device__ arrays — no cudaMalloc allowed)
__device__ __nv_bfloat16 g_ah[MDIM * S_DIM];        // A hi, K-major [m][s]
__device__ __nv_bfloat16 g_al[MDIM * S_DIM];        // A lo
__device__ __nv_bfloat16 g_bh[MDIM * S_DIM];        // B hi
__device__ __nv_bfloat16 g_bl[MDIM * S_DIM];        // B lo
__device__ __nv_bfloat16 g_oh[(size_t)65536 * 1024];  // outer hi [p][hk], 134 MB
__device__ __nv_bfloat16 g_ol[(size_t)65536 * 1024];  // outer lo
__device__ __nv_bfloat16 g_wh[CZ * 1024];           // w_out^T hi [z][k]
__device__ __nv_bfloat16 g_wl[CZ * 1024];           // w_out^T lo

// ---------------- HMMA helper: m16n8k16 bf16, fp32 accum -------------------
__device__ __forceinline__ void mma_bf16(float* c, const uint32_t* a, const uint32_t* b) {
    asm volatile(
        "mma.sync.aligned.m16n8k16.row.col.f32.bf16.bf16.f32 "
        "{%0,%1,%2,%3},{%4,%5,%6,%7},{%8,%9},{%0,%1,%2,%3};"
        : "+f"(c[0]), "+f"(c[1]), "+f"(c[2]), "+f"(c[3])
        : "r"(a[0]), "r"(a[1]), "r"(a[2]), "r"(a[3]), "r"(b[0]), "r"(b[1]));
}
__device__ __forceinline__ uint32_t pack_hi(float x, float y) {
    unsigned hx = __bfloat16_as_ushort(__float2bfloat16(x));
    unsigned hy = __bfloat16_as_ushort(__float2bfloat16(y));
    return hx | (hy << 16);
}
__device__ __forceinline__ uint32_t pack_lo(float x, float y) {
    float rx = x - __bfloat162float(__float2bfloat16(x));
    float ry = y - __bfloat162float(__float2bfloat16(y));
    unsigned lx = __bfloat16_as_ushort(__float2bfloat16(rx));
    unsigned ly = __bfloat16_as_ushort(__float2bfloat16(ry));
    return lx | (ly << 16);
}

// ---------------------------------------------------------------------------
// Kernel 1: LayerNorm + dual projection -> K-major bf16 hi/lo tiles.
// ---------------------------------------------------------------------------
__global__ __launch_bounds__(256) void k_proj(
    const float* __restrict__ m, const float* __restrict__ mask,
    const float* __restrict__ lnw, const float* __restrict__ lnb,
    const float* __restrict__ w1, const float* __restrict__ b1,
    const float* __restrict__ w2, const float* __restrict__ b2)
{
    __shared__ float mhs[16][CS];
    __shared__ float lnws[CS], lnbs[CS];

    int tid  = threadIdx.x;
    int lane = tid & 31;
    int wid  = tid >> 5;

    lnws[tid] = lnw[tid];
    lnbs[tid] = lnb[tid];
    __syncthreads();

    int r  = blockIdx.x & 255;
    int sg = blockIdx.x >> 8;      // 0..7

    #pragma unroll
    for (int rr = 0; rr < 2; rr++) {
        int rl  = wid * 2 + rr;            // 0..15
        int s   = sg * 16 + rl;
        int row = s * R_DIM + r;
        const float4* mrow = (const float4*)(m + (size_t)row * CS);
        float4 v0 = mrow[lane * 2];
        float4 v1 = mrow[lane * 2 + 1];
        float s1 = v0.x + v0.y + v0.z + v0.w + v1.x + v1.y + v1.z + v1.w;
        float s2 = v0.x*v0.x + v0.y*v0.y + v0.z*v0.z + v0.w*v0.w
                 + v1.x*v1.x + v1.y*v1.y + v1.z*v1.z + v1.w*v1.w;
        #pragma unroll
        for (int off = 16; off; off >>= 1) {
            s1 += __shfl_xor_sync(0xffffffffu, s1, off);
            s2 += __shfl_xor_sync(0xffffffffu, s2, off);
        }
        float mu   = s1 * (1.0f / CS);
        float var  = s2 * (1.0f / CS) - mu * mu;
        float rstd = rsqrtf(var + LN_EPS);
        int c0 = lane * 8;
        float t[8] = {v0.x, v0.y, v0.z, v0.w, v1.x, v1.y, v1.z, v1.w};
        #pragma unroll
        for (int q = 0; q < 8; q++) {
            int c = c0 + q;
            mhs[rl][c] = (t[q] - mu) * rstd * lnws[c] + lnbs[c];
        }
    }
    __syncthreads();

    int o  = tid & 63;
    int rg = tid >> 6;
    int h  = o & 31;
    const float* wp = (o < 32) ? (w1 + h) : (w2 + h);
    float acc0 = 0.f, acc1 = 0.f, acc2 = 0.f, acc3 = 0.f;
    #pragma unroll 8
    for (int c = 0; c < CS; c++) {
        float wv = __ldg(wp + c * CH);
        acc0 += mhs[rg * 4 + 0][c] * wv;
        acc1 += mhs[rg * 4 + 1][c] * wv;
        acc2 += mhs[rg * 4 + 2][c] * wv;
        acc3 += mhs[rg * 4 + 3][c] * wv;
    }
    float bias = (o < 32) ? b1[h] : b2[h];
    __nv_bfloat16* dh = (o < 32) ? g_ah : g_bh;
    __nv_bfloat16* dl = (o < 32) ? g_al : g_bl;
    float accs[4] = {acc0, acc1, acc2, acc3};
    int s0 = sg * 16 + rg * 4;

    float v0 = (accs[0] + bias) * mask[(s0 + 0) * R_DIM + r];
    float v1 = (accs[1] + bias) * mask[(s0 + 1) * R_DIM + r];
    float v2 = (accs[2] + bias) * mask[(s0 + 2) * R_DIM + r];
    float v3 = (accs[3] + bias) * mask[(s0 + 3) * R_DIM + r];

    size_t base = (size_t)(r * CH + h) * S_DIM + s0;
    *(uint2*)&dh[base] = make_uint2(pack_hi(v0, v1), pack_hi(v2, v3));
    *(uint2*)&dl[base] = make_uint2(pack_lo(v0, v1), pack_lo(v2, v3));
}

// ---------------------------------------------------------------------------
// Kernel 1b: transpose+convert w_out [k][z] fp32 -> g_wh/g_wl [z][k] bf16
// ---------------------------------------------------------------------------
__global__ void k_wprep(const float* __restrict__ w_out)
{
    __shared__ float t[32][33];
    int tx = threadIdx.x, ty = threadIdx.y;
    int k0 = blockIdx.x * 32, z0 = blockIdx.y * 32;
    t[ty][tx] = w_out[(size_t)(k0 + ty) * CZ + z0 + tx];
    __syncthreads();
    float v = t[tx][ty];                       // = w_out[k0+tx][z0+ty]
    __nv_bfloat16 hb = __float2bfloat16(v);
    __nv_bfloat16 lb = __float2bfloat16(v - __bfloat162float(hb));
    g_wh[(size_t)(z0 + ty) * 1024 + k0 + tx] = hb;
    g_wl[(size_t)(z0 + ty) * 1024 + k0 + tx] = lb;
}

// ---------------------------------------------------------------------------
// Kernel 2: outer contraction via HMMA bf16x3. C[m,n] = sum_s A[m,s]*B[n,s].
// Block 128x128, 8 warps (2m x 4n), warp tile 64x32, K chunks of 32.
// Epilogue writes g_oh/g_ol [p=(i*256+j)][h*32+kk] bf16 hi/lo.
// ---------------------------------------------------------------------------
#define RPAD 18   // u32 per smem row (36 bf16): conflict-free frag loads

__global__ __launch_bounds__(256) void k_gemm1_mma()
{
    __shared__ uint32_t sAh[128 * RPAD], sAl[128 * RPAD];
    __shared__ uint32_t sBh[128 * RPAD], sBl[128 * RPAD];

    int tid = threadIdx.x, lane = tid & 31, warp = tid >> 5;
    int g = lane >> 2, tg = lane & 3;
    int wm = warp & 1, wn = warp >> 1;
    int m0 = blockIdx.x * 128, n0 = blockIdx.y * 128;

    const uint4* pah = (const uint4*)g_ah;
    const uint4* pal = (const uint4*)g_al;
    const uint4* pbh = (const uint4*)g_bh;
    const uint4* pbl = (const uint4*)g_bl;

    float acc[4][4][4];
    #pragma unroll
    for (int a = 0; a < 4; a++)
        #pragma unroll
        for (int b = 0; b < 4; b++)
            #pragma unroll
            for (int c = 0; c < 4; c++) acc[a][b][c] = 0.f;

    for (int kc = 0; kc < 4; kc++) {
        if (kc) __syncthreads();
        #pragma unroll
        for (int u = 0; u < 2; u++) {
            int f   = tid * 2 + u;            // 0..511
            int row = f >> 2, q = f & 3;
            int so  = row * RPAD + q * 4;
            size_t ga = (size_t)(m0 + row) * 16 + kc * 4 + q;   // uint4 idx
            uint4 vh = pah[ga], vl = pal[ga];
            sAh[so] = vh.x; sAh[so+1] = vh.y; sAh[so+2] = vh.z; sAh[so+3] = vh.w;
            sAl[so] = vl.x; sAl[so+1] = vl.y; sAl[so+2] = vl.z; sAl[so+3] = vl.w;
            size_t gb = (size_t)(n0 + row) * 16 + kc * 4 + q;
            uint4 uh = pbh[gb], ul = pbl[gb];
            sBh[so] = uh.x; sBh[so+1] = uh.y; sBh[so+2] = uh.z; sBh[so+3] = uh.w;
            sBl[so] = ul.x; sBl[so+1] = ul.y; sBl[so+2] = ul.z; sBl[so+3] = ul.w;
        }
        __syncthreads();

        #pragma unroll
        for (int ks = 0; ks < 2; ks++) {
            uint32_t ah[4][4], al[4][4], bh[4][2], bl[4][2];
            #pragma unroll
            for (int mt = 0; mt < 4; mt++) {
                int r0 = (wm * 64 + mt * 16 + g) * RPAD;
                int p0 = ks * 8 + tg;
                ah[mt][0] = sAh[r0 + p0];
                ah[mt][1] = sAh[r0 + 8 * RPAD + p0];
                ah[mt][2] = sAh[r0 + p0 + 4];
                ah[mt][3] = sAh[r0 + 8 * RPAD + p0 + 4];
                al[mt][0] = sAl[r0 + p0];
                al[mt][1] = sAl[r0 + 8 * RPAD + p0];
                al[mt][2] = sAl[r0 + p0 + 4];
                al[mt][3] = sAl[r0 + 8 * RPAD + p0 + 4];
            }
            #pragma unroll
            for (int nt = 0; nt < 4; nt++) {
                int rn = (wn * 32 + nt * 8 + g) * RPAD;
                int p0 = ks * 8 + tg;
                bh[nt][0] = sBh[rn + p0];
                bh[nt][1] = sBh[rn + p0 + 4];
                bl[nt][0] = sBl[rn + p0];
                bl[nt][1] = sBl[rn + p0 + 4];
            }
            #pragma unroll
            for (int mt = 0; mt < 4; mt++)
                #pragma unroll
                for (int nt = 0; nt < 4; nt++) {
                    mma_bf16(acc[mt][nt], ah[mt], bh[nt]);
                    mma_bf16(acc[mt][nt], ah[mt], bl[nt]);
                    mma_bf16(acc[mt][nt], al[mt], bh[nt]);
                }
        }
    }

    // Epilogue: bf16 hi/lo into [i][j][h][kk]
    uint32_t* oh32 = (uint32_t*)g_oh;
    uint32_t* ol32 = (uint32_t*)g_ol;
    #pragma unroll
    for (int mt = 0; mt < 4; mt++) {
        int mbase = m0 + wm * 64 + mt * 16 + g;
        #pragma unroll
        for (int nt = 0; nt < 4; nt++) {
            int n  = n0 + wn * 32 + nt * 8 + 2 * tg;
            int j  = n >> 5, kk = n & 31;
            #pragma unroll
            for (int half = 0; half < 2; half++) {
                int mm = mbase + half * 8;
                int i  = mm >> 5, h = mm & 31;
                float cx = acc[mt][nt][half * 2 + 0];
                float cy = acc[mt][nt][half * 2 + 1];
                size_t idx = (size_t)(i * R_DIM + j) * 512 + h * 16 + (kk >> 1);
                oh32[idx] = pack_hi(cx, cy);
                ol32[idx] = pack_lo(cx, cy);
            }
        }
    }
}

// ---------------------------------------------------------------------------
// Kernel 3: output GEMM via HMMA bf16x3 + bias + mask-norm divide.
// Block: 128 p x 128 z, K=1024 chunks of 32. Same warp structure.
// ---------------------------------------------------------------------------
__global__ __launch_bounds__(256) void k_gemm2_mma(
    const float* __restrict__ mask, const float* __restrict__ b_out,
    float* __restrict__ out)
{
    __shared__ uint32_t sAh[128 * RPAD], sAl[128 * RPAD];
    __shared__ uint32_t sBh[128 * RPAD], sBl[128 * RPAD];
    __shared__ float norms[128];

    int tid = threadIdx.x, lane = tid & 31, warp = tid >> 5;
    int g = lane >> 2, tg = lane & 3;
    int wm = warp & 1, wn = warp >> 1;
    int p0 = blockIdx.x * 128;
    int i  = p0 >> 8;
    int j0 = p0 & 255;

    if (tid < 128) {
        float nacc = 0.f;
        #pragma unroll 4
        for (int s = 0; s < S_DIM; s++)
            nacc += mask[s * R_DIM + i] * mask[s * R_DIM + j0 + tid];
        norms[tid] = nacc;
    }

    const uint4* pah = (const uint4*)g_oh;
    const uint4* pal = (const uint4*)g_ol;
    const uint4* pbh = (const uint4*)g_wh;
    const uint4* pbl = (const uint4*)g_wl;

    float acc[4][4][4];
    #pragma unroll
    for (int a = 0; a < 4; a++)
        #pragma unroll
        for (int b = 0; b < 4; b++)
            #pragma unroll
            for (int c = 0; c < 4; c++) acc[a][b][c] = 0.f;

    for (int kc = 0; kc < 32; kc++) {
        __syncthreads();
        #pragma unroll
        for (int u = 0; u < 2; u++) {
            int f   = tid * 2 + u;
            int row = f >> 2, q = f & 3;
            int so  = row * RPAD + q * 4;
            size_t ga = (size_t)(p0 + row) * 128 + kc * 4 + q;   // 1024 bf16 = 128 uint4/row
            uint4 vh = pah[ga], vl = pal[ga];
            sAh[so] = vh.x; sAh[so+1] = vh.y; sAh[so+2] = vh.z; sAh[so+3] = vh.w;
            sAl[so] = vl.x; sAl[so+1] = vl.y; sAl[so+2] = vl.z; sAl[so+3] = vl.w;
            size_t gb = (size_t)row * 128 + kc * 4 + q;          // z rows 0..127
            uint4 uh = pbh[gb], ul = pbl[gb];
            sBh[so] = uh.x; sBh[so+1] = uh.y; sBh[so+2] = uh.z; sBh[so+3] = uh.w;
            sBl[so] = ul.x; sBl[so+1] = ul.y; sBl[so+2] = ul.z; sBl[so+3] = ul.w;
        }
        __syncthreads();

        #pragma unroll
        for (int ks = 0; ks < 2; ks++) {
            uint32_t ah[4][4], al[4][4], bh[4][2], bl[4][2];
            #pragma unroll
            for (int mt = 0; mt < 4; mt++) {
                int r0 = (wm * 64 + mt * 16 + g) * RPAD;
                int q0 = ks * 8 + tg;
                ah[mt][0] = sAh[r0 + q0];
                ah[mt][1] = sAh[r0 + 8 * RPAD + q0];
                ah[mt][2] = sAh[r0 + q0 + 4];
                ah[mt][3] = sAh[r0 + 8 * RPAD + q0 + 4];
                al[mt][0] = sAl[r0 + q0];
                al[mt][1] = sAl[r0 + 8 * RPAD + q0];
                al[mt][2] = sAl[r0 + q0 + 4];
                al[mt][3] = sAl[r0 + 8 * RPAD + q0 + 4];
            }
            #pragma unroll
            for (int nt = 0; nt < 4; nt++) {
                int rn = (wn * 32 + nt * 8 + g) * RPAD;
                int q0 = ks * 8 + tg;
                bh[nt][0] = sBh[rn + q0];
                bh[nt][1] = sBh[rn + q0 + 4];
                bl[nt][0] = sBl[rn + q0];
                bl[nt][1] = sBl[rn + q0 + 4];
            }
            #pragma unroll
            for (int mt = 0; mt < 4; mt++)
                #pragma unroll
                for (int nt = 0; nt < 4; nt++) {
                    mma_bf16(acc[mt][nt], ah[mt], bh[nt]);
                    mma_bf16(acc[mt][nt], ah[mt], bl[nt]);
                    mma_bf16(acc[mt][nt], al[mt], bh[nt]);
                }
        }
    }

    // Epilogue: bias + norm divide, fp32 out
    #pragma unroll
    for (int mt = 0; mt < 4; mt++) {
        int pl = wm * 64 + mt * 16 + g;
        #pragma unroll
        for (int nt = 0; nt < 4; nt++) {
            int z = wn * 32 + nt * 8 + 2 * tg;
            float2 bz = *(const float2*)&b_out[z];
            #pragma unroll
            for (int half = 0; half < 2; half++) {
                int pp = pl + half * 8;
                float inv = 1.0f / (MASK_EPS + norms[pp]);
                float cx = (acc[mt][nt][half * 2 + 0] + bz.x) * inv;
                float cy = (acc[mt][nt][half * 2 + 1] + bz.y) * inv;
                *(float2*)&out[(size_t)(p0 + pp) * CZ + z] = make_float2(cx, cy);
            }
        }
    }
}

// ---------------------------------------------------------------------------
extern "C" void kernel_launch(void* const* d_in, const int* in_sizes, int n_in,
                              void* d_out, int out_size)
{
    const float* m     = (const float*)d_in[0];
    const float* mask  = (const float*)d_in[1];
    const float* lnw   = (const float*)d_in[2];
    const float* lnb   = (const float*)d_in[3];
    const float* w1    = (const float*)d_in[4];
    const float* b1    = (const float*)d_in[5];
    const float* w2    = (const float*)d_in[6];
    const float* b2    = (const float*)d_in[7];
    const float* w_out = (const float*)d_in[8];
    const float* b_out = (const float*)d_in[9];
    float* out = (float*)d_out;

    k_wprep<<<dim3(32, 4), dim3(32, 32)>>>(w_out);
    k_proj<<<2048, 256>>>(m, mask, lnw, lnb, w1, b1, w2, b2);
    k_gemm1_mma<<<dim3(64, 64), 256>>>();
    k_gemm2_mma<<<512, 256>>>(mask, b_out, out);
}

// round 5
// speedup vs baseline: 1.6695x; 1.1596x over previous
#include <cuda_runtime.h>
#include <cuda_bf16.h>
#include <math.h>
#include <cstdint>

#define S_DIM 128
#define R_DIM 256
#define CS 256
#define CH 32
#define CZ 128
#define MDIM 8192           // R_DIM * CH
#define LN_EPS 1e-5f
#define MASK_EPS 1e-3f

// Scratch (static __device__ arrays — no cudaMalloc allowed)
__device__ __nv_bfloat16 g_ah[MDIM * S_DIM];        // A hi, K-major [m][s]
__device__ __nv_bfloat16 g_al[MDIM * S_DIM];        // A lo
__device__ __nv_bfloat16 g_bh[MDIM * S_DIM];        // B hi
__device__ __nv_bfloat16 g_bl[MDIM * S_DIM];        // B lo
__device__ __nv_bfloat16 g_oh[(size_t)65536 * 1024];  // outer hi [p][hk]
__device__ __nv_bfloat16 g_ol[(size_t)65536 * 1024];  // outer lo
__device__ __nv_bfloat16 g_wh[CZ * 1024];           // w_out^T hi [z][k]
__device__ __nv_bfloat16 g_wl[CZ * 1024];           // w_out^T lo

// ---------------- helpers ---------------------------------------------------
__device__ __forceinline__ void mma_bf16(float* c, const uint32_t* a, const uint32_t* b) {
    asm volatile(
        "mma.sync.aligned.m16n8k16.row.col.f32.bf16.bf16.f32 "
        "{%0,%1,%2,%3},{%4,%5,%6,%7},{%8,%9},{%0,%1,%2,%3};"
        : "+f"(c[0]), "+f"(c[1]), "+f"(c[2]), "+f"(c[3])
        : "r"(a[0]), "r"(a[1]), "r"(a[2]), "r"(a[3]), "r"(b[0]), "r"(b[1]));
}
__device__ __forceinline__ uint32_t pack_hi(float x, float y) {
    unsigned hx = __bfloat16_as_ushort(__float2bfloat16(x));
    unsigned hy = __bfloat16_as_ushort(__float2bfloat16(y));
    return hx | (hy << 16);
}
__device__ __forceinline__ uint32_t pack_lo(float x, float y) {
    float rx = x - __bfloat162float(__float2bfloat16(x));
    float ry = y - __bfloat162float(__float2bfloat16(y));
    unsigned lx = __bfloat16_as_ushort(__float2bfloat16(rx));
    unsigned ly = __bfloat16_as_ushort(__float2bfloat16(ry));
    return lx | (ly << 16);
}
__device__ __forceinline__ uint32_t smem_u32(const void* p) {
    uint32_t a;
    asm("{ .reg .u64 t; cvta.to.shared.u64 t, %1; cvt.u32.u64 %0, t; }"
        : "=r"(a) : "l"(p));
    return a;
}
__device__ __forceinline__ void cp16(uint32_t dst, const void* src) {
    asm volatile("cp.async.cg.shared.global [%0], [%1], 16;" :: "r"(dst), "l"(src));
}
#define CP_COMMIT() asm volatile("cp.async.commit_group;" ::: "memory")
#define CP_WAIT1()  asm volatile("cp.async.wait_group 1;" ::: "memory")
#define CP_WAIT0()  asm volatile("cp.async.wait_group 0;" ::: "memory")

// smem pipeline geometry (both GEMMs): per stage 4 arrays of 128 rows x 20 u32
#define RPAD 20
#define ARR_B   (128 * RPAD * 4)      // 10240 bytes per array
#define ST_B    (ARR_B * 4)           // 40960 bytes per stage
#define OFF_AH  0
#define OFF_AL  ARR_B
#define OFF_BH  (2 * ARR_B)
#define OFF_BL  (3 * ARR_B)
#define SMEM_PIPE (2 * ST_B)          // 81920 bytes

// ---------------------------------------------------------------------------
// Kernel 1: LayerNorm + dual projection -> K-major bf16 hi/lo tiles.
// ---------------------------------------------------------------------------
__global__ __launch_bounds__(256) void k_proj(
    const float* __restrict__ m, const float* __restrict__ mask,
    const float* __restrict__ lnw, const float* __restrict__ lnb,
    const float* __restrict__ w1, const float* __restrict__ b1,
    const float* __restrict__ w2, const float* __restrict__ b2)
{
    __shared__ float mhs[16][CS];
    __shared__ float lnws[CS], lnbs[CS];

    int tid  = threadIdx.x;
    int lane = tid & 31;
    int wid  = tid >> 5;

    lnws[tid] = lnw[tid];
    lnbs[tid] = lnb[tid];
    __syncthreads();

    int r  = blockIdx.x & 255;
    int sg = blockIdx.x >> 8;      // 0..7

    #pragma unroll
    for (int rr = 0; rr < 2; rr++) {
        int rl  = wid * 2 + rr;            // 0..15
        int s   = sg * 16 + rl;
        int row = s * R_DIM + r;
        const float4* mrow = (const float4*)(m + (size_t)row * CS);
        float4 v0 = mrow[lane * 2];
        float4 v1 = mrow[lane * 2 + 1];
        float s1 = v0.x + v0.y + v0.z + v0.w + v1.x + v1.y + v1.z + v1.w;
        float s2 = v0.x*v0.x + v0.y*v0.y + v0.z*v0.z + v0.w*v0.w
                 + v1.x*v1.x + v1.y*v1.y + v1.z*v1.z + v1.w*v1.w;
        #pragma unroll
        for (int off = 16; off; off >>= 1) {
            s1 += __shfl_xor_sync(0xffffffffu, s1, off);
            s2 += __shfl_xor_sync(0xffffffffu, s2, off);
        }
        float mu   = s1 * (1.0f / CS);
        float var  = s2 * (1.0f / CS) - mu * mu;
        float rstd = rsqrtf(var + LN_EPS);
        int c0 = lane * 8;
        float t[8] = {v0.x, v0.y, v0.z, v0.w, v1.x, v1.y, v1.z, v1.w};
        #pragma unroll
        for (int q = 0; q < 8; q++) {
            int c = c0 + q;
            mhs[rl][c] = (t[q] - mu) * rstd * lnws[c] + lnbs[c];
        }
    }
    __syncthreads();

    int o  = tid & 63;
    int rg = tid >> 6;
    int h  = o & 31;
    const float* wp = (o < 32) ? (w1 + h) : (w2 + h);
    float acc0 = 0.f, acc1 = 0.f, acc2 = 0.f, acc3 = 0.f;
    #pragma unroll 8
    for (int c = 0; c < CS; c++) {
        float wv = __ldg(wp + c * CH);
        acc0 += mhs[rg * 4 + 0][c] * wv;
        acc1 += mhs[rg * 4 + 1][c] * wv;
        acc2 += mhs[rg * 4 + 2][c] * wv;
        acc3 += mhs[rg * 4 + 3][c] * wv;
    }
    float bias = (o < 32) ? b1[h] : b2[h];
    __nv_bfloat16* dh = (o < 32) ? g_ah : g_bh;
    __nv_bfloat16* dl = (o < 32) ? g_al : g_bl;
    float accs[4] = {acc0, acc1, acc2, acc3};
    int s0 = sg * 16 + rg * 4;

    float v0 = (accs[0] + bias) * mask[(s0 + 0) * R_DIM + r];
    float v1 = (accs[1] + bias) * mask[(s0 + 1) * R_DIM + r];
    float v2 = (accs[2] + bias) * mask[(s0 + 2) * R_DIM + r];
    float v3 = (accs[3] + bias) * mask[(s0 + 3) * R_DIM + r];

    size_t base = (size_t)(r * CH + h) * S_DIM + s0;
    *(uint2*)&dh[base] = make_uint2(pack_hi(v0, v1), pack_hi(v2, v3));
    *(uint2*)&dl[base] = make_uint2(pack_lo(v0, v1), pack_lo(v2, v3));
}

// ---------------------------------------------------------------------------
// Kernel 1b: transpose+convert w_out [k][z] fp32 -> g_wh/g_wl [z][k] bf16
// ---------------------------------------------------------------------------
__global__ void k_wprep(const float* __restrict__ w_out)
{
    __shared__ float t[32][33];
    int tx = threadIdx.x, ty = threadIdx.y;
    int k0 = blockIdx.x * 32, z0 = blockIdx.y * 32;
    t[ty][tx] = w_out[(size_t)(k0 + ty) * CZ + z0 + tx];
    __syncthreads();
    float v = t[tx][ty];                       // = w_out[k0+tx][z0+ty]
    __nv_bfloat16 hb = __float2bfloat16(v);
    __nv_bfloat16 lb = __float2bfloat16(v - __bfloat162float(hb));
    g_wh[(size_t)(z0 + ty) * 1024 + k0 + tx] = hb;
    g_wl[(size_t)(z0 + ty) * 1024 + k0 + tx] = lb;
}

// ---------------------------------------------------------------------------
// Shared compute core: one K-chunk (32 k) of bf16x3 HMMA on a 128x128 tile.
// ---------------------------------------------------------------------------
__device__ __forceinline__ void mma_chunk(
    const char* stage, int wm, int wn, int g, int tg, float acc[4][4][4])
{
    const uint32_t* sAh = (const uint32_t*)(stage + OFF_AH);
    const uint32_t* sAl = (const uint32_t*)(stage + OFF_AL);
    const uint32_t* sBh = (const uint32_t*)(stage + OFF_BH);
    const uint32_t* sBl = (const uint32_t*)(stage + OFF_BL);

    #pragma unroll
    for (int ks = 0; ks < 2; ks++) {
        uint32_t ah[4][4], al[4][4], bh[4][2], bl[4][2];
        #pragma unroll
        for (int mt = 0; mt < 4; mt++) {
            int r0 = (wm * 64 + mt * 16 + g) * RPAD;
            int q0 = ks * 8 + tg;
            ah[mt][0] = sAh[r0 + q0];
            ah[mt][1] = sAh[r0 + 8 * RPAD + q0];
            ah[mt][2] = sAh[r0 + q0 + 4];
            ah[mt][3] = sAh[r0 + 8 * RPAD + q0 + 4];
            al[mt][0] = sAl[r0 + q0];
            al[mt][1] = sAl[r0 + 8 * RPAD + q0];
            al[mt][2] = sAl[r0 + q0 + 4];
            al[mt][3] = sAl[r0 + 8 * RPAD + q0 + 4];
        }
        #pragma unroll
        for (int nt = 0; nt < 4; nt++) {
            int rn = (wn * 32 + nt * 8 + g) * RPAD;
            int q0 = ks * 8 + tg;
            bh[nt][0] = sBh[rn + q0];
            bh[nt][1] = sBh[rn + q0 + 4];
            bl[nt][0] = sBl[rn + q0];
            bl[nt][1] = sBl[rn + q0 + 4];
        }
        #pragma unroll
        for (int mt = 0; mt < 4; mt++)
            #pragma unroll
            for (int nt = 0; nt < 4; nt++) {
                mma_bf16(acc[mt][nt], ah[mt], bh[nt]);
                mma_bf16(acc[mt][nt], ah[mt], bl[nt]);
                mma_bf16(acc[mt][nt], al[mt], bh[nt]);
            }
    }
}

// ---------------------------------------------------------------------------
// Kernel 2: outer contraction via HMMA bf16x3, cp.async double-buffered.
// ---------------------------------------------------------------------------
__global__ __launch_bounds__(256) void k_gemm1_mma()
{
    extern __shared__ char smem[];
    uint32_t sb = smem_u32(smem);

    int tid = threadIdx.x, lane = tid & 31, warp = tid >> 5;
    int g = lane >> 2, tg = lane & 3;
    int wm = warp & 1, wn = warp >> 1;
    int m0 = blockIdx.x * 128, n0 = blockIdx.y * 128;

    const uint4* pah = (const uint4*)g_ah;
    const uint4* pal = (const uint4*)g_al;
    const uint4* pbh = (const uint4*)g_bh;
    const uint4* pbl = (const uint4*)g_bl;

    int row = tid >> 1;                 // 0..127 (2 threads per row)
    int qb  = (tid & 1) * 2;            // q base: 0 or 2

    float acc[4][4][4];
    #pragma unroll
    for (int a = 0; a < 4; a++)
        #pragma unroll
        for (int b = 0; b < 4; b++)
            #pragma unroll
            for (int c = 0; c < 4; c++) acc[a][b][c] = 0.f;

    // prologue: stage 0 = chunk 0
    #pragma unroll
    for (int u = 0; u < 2; u++) {
        int q = qb + u;
        uint32_t so = sb + (uint32_t)(row * 80 + q * 16);
        size_t ga = (size_t)(m0 + row) * 16 + q;
        size_t gb = (size_t)(n0 + row) * 16 + q;
        cp16(so + OFF_AH, pah + ga);
        cp16(so + OFF_AL, pal + ga);
        cp16(so + OFF_BH, pbh + gb);
        cp16(so + OFF_BL, pbl + gb);
    }
    CP_COMMIT();

    #pragma unroll
    for (int kc = 0; kc < 4; kc++) {
        if (kc + 1 < 4) {
            uint32_t stb = sb + ((kc + 1) & 1) * ST_B;
            #pragma unroll
            for (int u = 0; u < 2; u++) {
                int q = qb + u;
                uint32_t so = stb + (uint32_t)(row * 80 + q * 16);
                size_t ga = (size_t)(m0 + row) * 16 + (kc + 1) * 4 + q;
                size_t gb = (size_t)(n0 + row) * 16 + (kc + 1) * 4 + q;
                cp16(so + OFF_AH, pah + ga);
                cp16(so + OFF_AL, pal + ga);
                cp16(so + OFF_BH, pbh + gb);
                cp16(so + OFF_BL, pbl + gb);
            }
            CP_COMMIT();
            CP_WAIT1();
        } else {
            CP_WAIT0();
        }
        __syncthreads();
        mma_chunk(smem + (kc & 1) * ST_B, wm, wn, g, tg, acc);
        __syncthreads();
    }

    // Epilogue: bf16 hi/lo into [i][j][h][kk]
    uint32_t* oh32 = (uint32_t*)g_oh;
    uint32_t* ol32 = (uint32_t*)g_ol;
    #pragma unroll
    for (int mt = 0; mt < 4; mt++) {
        int mbase = m0 + wm * 64 + mt * 16 + g;
        #pragma unroll
        for (int nt = 0; nt < 4; nt++) {
            int n  = n0 + wn * 32 + nt * 8 + 2 * tg;
            int j  = n >> 5, kk = n & 31;
            #pragma unroll
            for (int half = 0; half < 2; half++) {
                int mm = mbase + half * 8;
                int i  = mm >> 5, h = mm & 31;
                float cx = acc[mt][nt][half * 2 + 0];
                float cy = acc[mt][nt][half * 2 + 1];
                size_t idx = (size_t)(i * R_DIM + j) * 512 + h * 16 + (kk >> 1);
                oh32[idx] = pack_hi(cx, cy);
                ol32[idx] = pack_lo(cx, cy);
            }
        }
    }
}

// ---------------------------------------------------------------------------
// Kernel 3: output GEMM via HMMA bf16x3 + bias + mask-norm, cp.async pipeline.
// ---------------------------------------------------------------------------
__global__ __launch_bounds__(256) void k_gemm2_mma(
    const float* __restrict__ mask, const float* __restrict__ b_out,
    float* __restrict__ out)
{
    extern __shared__ char smem[];
    __shared__ float norms[128];
    uint32_t sb = smem_u32(smem);

    int tid = threadIdx.x, lane = tid & 31, warp = tid >> 5;
    int g = lane >> 2, tg = lane & 3;
    int wm = warp & 1, wn = warp >> 1;
    int p0 = blockIdx.x * 128;
    int i  = p0 >> 8;
    int j0 = p0 & 255;

    if (tid < 128) {
        float nacc = 0.f;
        #pragma unroll 4
        for (int s = 0; s < S_DIM; s++)
            nacc += mask[s * R_DIM + i] * mask[s * R_DIM + j0 + tid];
        norms[tid] = nacc;
    }

    const uint4* pah = (const uint4*)g_oh;
    const uint4* pal = (const uint4*)g_ol;
    const uint4* pbh = (const uint4*)g_wh;
    const uint4* pbl = (const uint4*)g_wl;

    int row = tid >> 1;
    int qb  = (tid & 1) * 2;

    float acc[4][4][4];
    #pragma unroll
    for (int a = 0; a < 4; a++)
        #pragma unroll
        for (int b = 0; b < 4; b++)
            #pragma unroll
            for (int c = 0; c < 4; c++) acc[a][b][c] = 0.f;

    // prologue: chunk 0
    #pragma unroll
    for (int u = 0; u < 2; u++) {
        int q = qb + u;
        uint32_t so = sb + (uint32_t)(row * 80 + q * 16);
        size_t ga = (size_t)(p0 + row) * 128 + q;
        size_t gb = (size_t)row * 128 + q;
        cp16(so + OFF_AH, pah + ga);
        cp16(so + OFF_AL, pal + ga);
        cp16(so + OFF_BH, pbh + gb);
        cp16(so + OFF_BL, pbl + gb);
    }
    CP_COMMIT();

    for (int kc = 0; kc < 32; kc++) {
        if (kc + 1 < 32) {
            uint32_t stb = sb + ((kc + 1) & 1) * ST_B;
            #pragma unroll
            for (int u = 0; u < 2; u++) {
                int q = qb + u;
                uint32_t so = stb + (uint32_t)(row * 80 + q * 16);
                size_t ga = (size_t)(p0 + row) * 128 + (kc + 1) * 4 + q;
                size_t gb = (size_t)row * 128 + (kc + 1) * 4 + q;
                cp16(so + OFF_AH, pah + ga);
                cp16(so + OFF_AL, pal + ga);
                cp16(so + OFF_BH, pbh + gb);
                cp16(so + OFF_BL, pbl + gb);
            }
            CP_COMMIT();
            CP_WAIT1();
        } else {
            CP_WAIT0();
        }
        __syncthreads();
        mma_chunk(smem + (kc & 1) * ST_B, wm, wn, g, tg, acc);
        __syncthreads();
    }

    // Epilogue: bias + norm divide, fp32 out
    #pragma unroll
    for (int mt = 0; mt < 4; mt++) {
        int pl = wm * 64 + mt * 16 + g;
        #pragma unroll
        for (int nt = 0; nt < 4; nt++) {
            int z = wn * 32 + nt * 8 + 2 * tg;
            float2 bz = *(const float2*)&b_out[z];
            #pragma unroll
            for (int half = 0; half < 2; half++) {
                int pp = pl + half * 8;
                float inv = 1.0f / (MASK_EPS + norms[pp]);
                float cx = (acc[mt][nt][half * 2 + 0] + bz.x) * inv;
                float cy = (acc[mt][nt][half * 2 + 1] + bz.y) * inv;
                *(float2*)&out[(size_t)(p0 + pp) * CZ + z] = make_float2(cx, cy);
            }
        }
    }
}

// ---------------------------------------------------------------------------
extern "C" void kernel_launch(void* const* d_in, const int* in_sizes, int n_in,
                              void* d_out, int out_size)
{
    const float* m     = (const float*)d_in[0];
    const float* mask  = (const float*)d_in[1];
    const float* lnw   = (const float*)d_in[2];
    const float* lnb   = (const float*)d_in[3];
    const float* w1    = (const float*)d_in[4];
    const float* b1    = (const float*)d_in[5];
    const float* w2    = (const float*)d_in[6];
    const float* b2    = (const float*)d_in[7];
    const float* w_out = (const float*)d_in[8];
    const float* b_out = (const float*)d_in[9];
    float* out = (float*)d_out;

    static int attr_done = 0;
    if (!attr_done) {
        cudaFuncSetAttribute(k_gemm1_mma,
            cudaFuncAttributeMaxDynamicSharedMemorySize, SMEM_PIPE);
        cudaFuncSetAttribute(k_gemm2_mma,
            cudaFuncAttributeMaxDynamicSharedMemorySize, SMEM_PIPE);
        attr_done = 1;
    }

    k_wprep<<<dim3(32, 4), dim3(32, 32)>>>(w_out);
    k_proj<<<2048, 256>>>(m, mask, lnw, lnb, w1, b1, w2, b2);
    k_gemm1_mma<<<dim3(64, 64), 256, SMEM_PIPE>>>();
    k_gemm2_mma<<<512, 256, SMEM_PIPE>>>(mask, b_out, out);
}

// round 6
// speedup vs baseline: 1.8438x; 1.1044x over previous
#include <cuda_runtime.h>
#include <cuda_bf16.h>
#include <math.h>
#include <cstdint>

#define S_DIM 128
#define R_DIM 256
#define CS 256
#define CH 32
#define CZ 128
#define MDIM 8192           // R_DIM * CH
#define LN_EPS 1e-5f
#define MASK_EPS 1e-3f

// Scratch (static __device__ arrays — no cudaMalloc allowed)
__device__ __nv_bfloat16 g_ah[MDIM * S_DIM];        // A hi, K-major [m][s]
__device__ __nv_bfloat16 g_al[MDIM * S_DIM];        // A lo
__device__ __nv_bfloat16 g_bh[MDIM * S_DIM];        // B hi
__device__ __nv_bfloat16 g_bl[MDIM * S_DIM];        // B lo
__device__ __nv_bfloat16 g_oh[(size_t)65536 * 1024];  // outer hi [p][hk]
__device__ __nv_bfloat16 g_ol[(size_t)65536 * 1024];  // outer lo
__device__ __nv_bfloat16 g_wh[CZ * 1024];           // w_out^T hi [z][k]
__device__ __nv_bfloat16 g_wl[CZ * 1024];           // w_out^T lo

// ---------------- helpers ---------------------------------------------------
__device__ __forceinline__ void mma_bf16(float* c, const uint32_t* a, const uint32_t* b) {
    asm volatile(
        "mma.sync.aligned.m16n8k16.row.col.f32.bf16.bf16.f32 "
        "{%0,%1,%2,%3},{%4,%5,%6,%7},{%8,%9},{%0,%1,%2,%3};"
        : "+f"(c[0]), "+f"(c[1]), "+f"(c[2]), "+f"(c[3])
        : "r"(a[0]), "r"(a[1]), "r"(a[2]), "r"(a[3]), "r"(b[0]), "r"(b[1]));
}
__device__ __forceinline__ uint32_t pack_hi(float x, float y) {
    unsigned hx = __bfloat16_as_ushort(__float2bfloat16(x));
    unsigned hy = __bfloat16_as_ushort(__float2bfloat16(y));
    return hx | (hy << 16);
}
__device__ __forceinline__ uint32_t pack_lo(float x, float y) {
    float rx = x - __bfloat162float(__float2bfloat16(x));
    float ry = y - __bfloat162float(__float2bfloat16(y));
    unsigned lx = __bfloat16_as_ushort(__float2bfloat16(rx));
    unsigned ly = __bfloat16_as_ushort(__float2bfloat16(ry));
    return lx | (ly << 16);
}
__device__ __forceinline__ uint32_t smem_u32(const void* p) {
    uint32_t a;
    asm("{ .reg .u64 t; cvta.to.shared.u64 t, %1; cvt.u32.u64 %0, t; }"
        : "=r"(a) : "l"(p));
    return a;
}
__device__ __forceinline__ void cp16(uint32_t dst, const void* src) {
    asm volatile("cp.async.cg.shared.global [%0], [%1], 16;" :: "r"(dst), "l"(src));
}
#define CP_COMMIT() asm volatile("cp.async.commit_group;" ::: "memory")
#define CP_WAIT2()  asm volatile("cp.async.wait_group 2;" ::: "memory")

// smem pipeline: K-chunk 16, 4 stages. Per stage: 4 arrays of 128 rows.
// Row = 16 bf16 = 32B data + 16B pad = 48B (RPAD=12 u32) -> conflict-free.
#define RPAD 12
#define ROW_B 48
#define ARR_B   (128 * ROW_B)         // 6144 B per array
#define ST_B    (ARR_B * 4)           // 24576 B per stage
#define OFF_AH  0
#define OFF_AL  ARR_B
#define OFF_BH  (2 * ARR_B)
#define OFF_BL  (3 * ARR_B)
#define NSTAGE  4
#define SMEM_PIPE (NSTAGE * ST_B)     // 98304 B

// ---------------------------------------------------------------------------
// Kernel 1: LayerNorm + dual projection -> K-major bf16 hi/lo tiles.
// Block: one r x 32 s-rows. Thread: 2 h-outputs x 4 s-rows (FMA:LDS = 2:1).
// ---------------------------------------------------------------------------
__global__ __launch_bounds__(256) void k_proj(
    const float* __restrict__ m, const float* __restrict__ mask,
    const float* __restrict__ lnw, const float* __restrict__ lnb,
    const float* __restrict__ w1, const float* __restrict__ b1,
    const float* __restrict__ w2, const float* __restrict__ b2)
{
    __shared__ float mhs[32][CS];     // 32 KB
    __shared__ float lnws[CS], lnbs[CS];

    int tid  = threadIdx.x;
    int lane = tid & 31;
    int wid  = tid >> 5;

    lnws[tid] = lnw[tid];
    lnbs[tid] = lnb[tid];
    __syncthreads();

    int r  = blockIdx.x & 255;
    int sg = blockIdx.x >> 8;      // 0..3

    #pragma unroll
    for (int rr = 0; rr < 4; rr++) {
        int rl  = wid * 4 + rr;            // 0..31
        int s   = sg * 32 + rl;
        int row = s * R_DIM + r;
        const float4* mrow = (const float4*)(m + (size_t)row * CS);
        float4 v0 = mrow[lane * 2];
        float4 v1 = mrow[lane * 2 + 1];
        float s1 = v0.x + v0.y + v0.z + v0.w + v1.x + v1.y + v1.z + v1.w;
        float s2 = v0.x*v0.x + v0.y*v0.y + v0.z*v0.z + v0.w*v0.w
                 + v1.x*v1.x + v1.y*v1.y + v1.z*v1.z + v1.w*v1.w;
        #pragma unroll
        for (int off = 16; off; off >>= 1) {
            s1 += __shfl_xor_sync(0xffffffffu, s1, off);
            s2 += __shfl_xor_sync(0xffffffffu, s2, off);
        }
        float mu   = s1 * (1.0f / CS);
        float var  = s2 * (1.0f / CS) - mu * mu;
        float rstd = rsqrtf(var + LN_EPS);
        int c0 = lane * 8;
        float t[8] = {v0.x, v0.y, v0.z, v0.w, v1.x, v1.y, v1.z, v1.w};
        #pragma unroll
        for (int q = 0; q < 8; q++) {
            int c = c0 + q;
            mhs[rl][c] = (t[q] - mu) * rstd * lnws[c] + lnbs[c];
        }
    }
    __syncthreads();

    int p  = tid & 31;                  // output-pair index
    int rg = tid >> 5;                  // 0..7 -> 4 s-rows each
    bool isA = (p < 16);
    int h0 = isA ? (2 * p) : (2 * (p - 16));
    const float* wb = isA ? w1 : w2;

    float acc[4][2];
    #pragma unroll
    for (int j = 0; j < 4; j++) { acc[j][0] = 0.f; acc[j][1] = 0.f; }

    #pragma unroll 4
    for (int c = 0; c < CS; c++) {
        float2 wv = *(const float2*)(wb + c * CH + h0);
        #pragma unroll
        for (int j = 0; j < 4; j++) {
            float mv = mhs[rg * 4 + j][c];
            acc[j][0] += mv * wv.x;
            acc[j][1] += mv * wv.y;
        }
    }

    float2 bias = *(const float2*)((isA ? b1 : b2) + h0);
    __nv_bfloat16* dh = isA ? g_ah : g_bh;
    __nv_bfloat16* dl = isA ? g_al : g_bl;
    int s0 = sg * 32 + rg * 4;

    float va[4], vb2[4];
    #pragma unroll
    for (int j = 0; j < 4; j++) {
        float mk = mask[(s0 + j) * R_DIM + r];
        va[j]  = (acc[j][0] + bias.x) * mk;
        vb2[j] = (acc[j][1] + bias.y) * mk;
    }
    size_t base0 = (size_t)(r * CH + h0) * S_DIM + s0;
    *(uint2*)&dh[base0]         = make_uint2(pack_hi(va[0], va[1]), pack_hi(va[2], va[3]));
    *(uint2*)&dl[base0]         = make_uint2(pack_lo(va[0], va[1]), pack_lo(va[2], va[3]));
    *(uint2*)&dh[base0 + S_DIM] = make_uint2(pack_hi(vb2[0], vb2[1]), pack_hi(vb2[2], vb2[3]));
    *(uint2*)&dl[base0 + S_DIM] = make_uint2(pack_lo(vb2[0], vb2[1]), pack_lo(vb2[2], vb2[3]));
}

// ---------------------------------------------------------------------------
// Kernel 1b: transpose+convert w_out [k][z] fp32 -> g_wh/g_wl [z][k] bf16
// ---------------------------------------------------------------------------
__global__ void k_wprep(const float* __restrict__ w_out)
{
    __shared__ float t[32][33];
    int tx = threadIdx.x, ty = threadIdx.y;
    int k0 = blockIdx.x * 32, z0 = blockIdx.y * 32;
    t[ty][tx] = w_out[(size_t)(k0 + ty) * CZ + z0 + tx];
    __syncthreads();
    float v = t[tx][ty];                       // = w_out[k0+tx][z0+ty]
    __nv_bfloat16 hb = __float2bfloat16(v);
    __nv_bfloat16 lb = __float2bfloat16(v - __bfloat162float(hb));
    g_wh[(size_t)(z0 + ty) * 1024 + k0 + tx] = hb;
    g_wl[(size_t)(z0 + ty) * 1024 + k0 + tx] = lb;
}

// ---------------------------------------------------------------------------
// One K-chunk (16 k) of bf16x3 HMMA on a 128x128 tile.
// ---------------------------------------------------------------------------
__device__ __forceinline__ void mma_chunk16(
    const char* stage, int wm, int wn, int g, int tg, float acc[4][4][4])
{
    const uint32_t* sAh = (const uint32_t*)(stage + OFF_AH);
    const uint32_t* sAl = (const uint32_t*)(stage + OFF_AL);
    const uint32_t* sBh = (const uint32_t*)(stage + OFF_BH);
    const uint32_t* sBl = (const uint32_t*)(stage + OFF_BL);

    uint32_t ah[4][4], al[4][4], bh[4][2], bl[4][2];
    #pragma unroll
    for (int mt = 0; mt < 4; mt++) {
        int r0 = (wm * 64 + mt * 16 + g) * RPAD;
        ah[mt][0] = sAh[r0 + tg];
        ah[mt][1] = sAh[r0 + 8 * RPAD + tg];
        ah[mt][2] = sAh[r0 + tg + 4];
        ah[mt][3] = sAh[r0 + 8 * RPAD + tg + 4];
        al[mt][0] = sAl[r0 + tg];
        al[mt][1] = sAl[r0 + 8 * RPAD + tg];
        al[mt][2] = sAl[r0 + tg + 4];
        al[mt][3] = sAl[r0 + 8 * RPAD + tg + 4];
    }
    #pragma unroll
    for (int nt = 0; nt < 4; nt++) {
        int rn = (wn * 32 + nt * 8 + g) * RPAD;
        bh[nt][0] = sBh[rn + tg];
        bh[nt][1] = sBh[rn + tg + 4];
        bl[nt][0] = sBl[rn + tg];
        bl[nt][1] = sBl[rn + tg + 4];
    }
    #pragma unroll
    for (int mt = 0; mt < 4; mt++)
        #pragma unroll
        for (int nt = 0; nt < 4; nt++) {
            mma_bf16(acc[mt][nt], ah[mt], bh[nt]);
            mma_bf16(acc[mt][nt], ah[mt], bl[nt]);
            mma_bf16(acc[mt][nt], al[mt], bh[nt]);
        }
}

// ---------------------------------------------------------------------------
// Kernel 2: outer contraction via HMMA bf16x3, 4-stage cp.async pipeline.
// ---------------------------------------------------------------------------
__global__ __launch_bounds__(256, 2) void k_gemm1_mma()
{
    extern __shared__ char smem[];
    uint32_t sb = smem_u32(smem);

    int tid = threadIdx.x, lane = tid & 31, warp = tid >> 5;
    int g = lane >> 2, tg = lane & 3;
    int wm = warp & 1, wn = warp >> 1;
    int m0 = blockIdx.x * 128, n0 = blockIdx.y * 128;

    const uint4* pah = (const uint4*)g_ah;
    const uint4* pal = (const uint4*)g_al;
    const uint4* pbh = (const uint4*)g_bh;
    const uint4* pbl = (const uint4*)g_bl;

    int row  = tid >> 1;                // 0..127
    int half = tid & 1;                 // 16B half within 32B chunk-row
    uint32_t dro = (uint32_t)(row * ROW_B + half * 16);

    float acc[4][4][4];
    #pragma unroll
    for (int a = 0; a < 4; a++)
        #pragma unroll
        for (int b = 0; b < 4; b++)
            #pragma unroll
            for (int c = 0; c < 4; c++) acc[a][b][c] = 0.f;

    // prologue: prefetch chunks 0..2
    #pragma unroll
    for (int pc = 0; pc < NSTAGE - 1; pc++) {
        uint32_t so = sb + pc * ST_B + dro;
        size_t ga = (size_t)(m0 + row) * 16 + pc * 2 + half;
        size_t gb = (size_t)(n0 + row) * 16 + pc * 2 + half;
        cp16(so + OFF_AH, pah + ga);
        cp16(so + OFF_AL, pal + ga);
        cp16(so + OFF_BH, pbh + gb);
        cp16(so + OFF_BL, pbl + gb);
        CP_COMMIT();
    }

    #pragma unroll
    for (int kc = 0; kc < 8; kc++) {
        CP_WAIT2();
        __syncthreads();
        int kp = kc + NSTAGE - 1;
        if (kp < 8) {
            uint32_t so = sb + (kp & 3) * ST_B + dro;
            size_t ga = (size_t)(m0 + row) * 16 + kp * 2 + half;
            size_t gb = (size_t)(n0 + row) * 16 + kp * 2 + half;
            cp16(so + OFF_AH, pah + ga);
            cp16(so + OFF_AL, pal + ga);
            cp16(so + OFF_BH, pbh + gb);
            cp16(so + OFF_BL, pbl + gb);
        }
        CP_COMMIT();
        mma_chunk16(smem + (kc & 3) * ST_B, wm, wn, g, tg, acc);
    }

    // Epilogue: bf16 hi/lo into [i][j][h][kk]
    uint32_t* oh32 = (uint32_t*)g_oh;
    uint32_t* ol32 = (uint32_t*)g_ol;
    #pragma unroll
    for (int mt = 0; mt < 4; mt++) {
        int mbase = m0 + wm * 64 + mt * 16 + g;
        #pragma unroll
        for (int nt = 0; nt < 4; nt++) {
            int n  = n0 + wn * 32 + nt * 8 + 2 * tg;
            int j  = n >> 5, kk = n & 31;
            #pragma unroll
            for (int hf = 0; hf < 2; hf++) {
                int mm = mbase + hf * 8;
                int i  = mm >> 5, h = mm & 31;
                float cx = acc[mt][nt][hf * 2 + 0];
                float cy = acc[mt][nt][hf * 2 + 1];
                size_t idx = (size_t)(i * R_DIM + j) * 512 + h * 16 + (kk >> 1);
                oh32[idx] = pack_hi(cx, cy);
                ol32[idx] = pack_lo(cx, cy);
            }
        }
    }
}

// ---------------------------------------------------------------------------
// Kernel 3: output GEMM via HMMA bf16x3 + bias + mask-norm, 4-stage pipeline.
// ---------------------------------------------------------------------------
__global__ __launch_bounds__(256, 2) void k_gemm2_mma(
    const float* __restrict__ mask, const float* __restrict__ b_out,
    float* __restrict__ out)
{
    extern __shared__ char smem[];
    __shared__ float norms[128];
    uint32_t sb = smem_u32(smem);

    int tid = threadIdx.x, lane = tid & 31, warp = tid >> 5;
    int g = lane >> 2, tg = lane & 3;
    int wm = warp & 1, wn = warp >> 1;
    int p0 = blockIdx.x * 128;
    int i  = p0 >> 8;
    int j0 = p0 & 255;

    if (tid < 128) {
        float nacc = 0.f;
        #pragma unroll 4
        for (int s = 0; s < S_DIM; s++)
            nacc += mask[s * R_DIM + i] * mask[s * R_DIM + j0 + tid];
        norms[tid] = nacc;
    }

    const uint4* pah = (const uint4*)g_oh;
    const uint4* pal = (const uint4*)g_ol;
    const uint4* pbh = (const uint4*)g_wh;
    const uint4* pbl = (const uint4*)g_wl;

    int row  = tid >> 1;
    int half = tid & 1;
    uint32_t dro = (uint32_t)(row * ROW_B + half * 16);

    float acc[4][4][4];
    #pragma unroll
    for (int a = 0; a < 4; a++)
        #pragma unroll
        for (int b = 0; b < 4; b++)
            #pragma unroll
            for (int c = 0; c < 4; c++) acc[a][b][c] = 0.f;

    // prologue
    #pragma unroll
    for (int pc = 0; pc < NSTAGE - 1; pc++) {
        uint32_t so = sb + pc * ST_B + dro;
        size_t ga = (size_t)(p0 + row) * 128 + pc * 2 + half;
        size_t gb = (size_t)row * 128 + pc * 2 + half;
        cp16(so + OFF_AH, pah + ga);
        cp16(so + OFF_AL, pal + ga);
        cp16(so + OFF_BH, pbh + gb);
        cp16(so + OFF_BL, pbl + gb);
        CP_COMMIT();
    }

    for (int kc = 0; kc < 64; kc++) {
        CP_WAIT2();
        __syncthreads();
        int kp = kc + NSTAGE - 1;
        if (kp < 64) {
            uint32_t so = sb + (kp & 3) * ST_B + dro;
            size_t ga = (size_t)(p0 + row) * 128 + kp * 2 + half;
            size_t gb = (size_t)row * 128 + kp * 2 + half;
            cp16(so + OFF_AH, pah + ga);
            cp16(so + OFF_AL, pal + ga);
            cp16(so + OFF_BH, pbh + gb);
            cp16(so + OFF_BL, pbl + gb);
        }
        CP_COMMIT();
        mma_chunk16(smem + (kc & 3) * ST_B, wm, wn, g, tg, acc);
    }

    // Epilogue: bias + norm divide, fp32 out
    #pragma unroll
    for (int mt = 0; mt < 4; mt++) {
        int pl = wm * 64 + mt * 16 + g;
        #pragma unroll
        for (int nt = 0; nt < 4; nt++) {
            int z = wn * 32 + nt * 8 + 2 * tg;
            float2 bz = *(const float2*)&b_out[z];
            #pragma unroll
            for (int hf = 0; hf < 2; hf++) {
                int pp = pl + hf * 8;
                float inv = 1.0f / (MASK_EPS + norms[pp]);
                float cx = (acc[mt][nt][hf * 2 + 0] + bz.x) * inv;
                float cy = (acc[mt][nt][hf * 2 + 1] + bz.y) * inv;
                *(float2*)&out[(size_t)(p0 + pp) * CZ + z] = make_float2(cx, cy);
            }
        }
    }
}

// ---------------------------------------------------------------------------
extern "C" void kernel_launch(void* const* d_in, const int* in_sizes, int n_in,
                              void* d_out, int out_size)
{
    const float* m     = (const float*)d_in[0];
    const float* mask  = (const float*)d_in[1];
    const float* lnw   = (const float*)d_in[2];
    const float* lnb   = (const float*)d_in[3];
    const float* w1    = (const float*)d_in[4];
    const float* b1    = (const float*)d_in[5];
    const float* w2    = (const float*)d_in[6];
    const float* b2    = (const float*)d_in[7];
    const float* w_out = (const float*)d_in[8];
    const float* b_out = (const float*)d_in[9];
    float* out = (float*)d_out;

    static int attr_done = 0;
    if (!attr_done) {
        cudaFuncSetAttribute(k_gemm1_mma,
            cudaFuncAttributeMaxDynamicSharedMemorySize, SMEM_PIPE);
        cudaFuncSetAttribute(k_gemm2_mma,
            cudaFuncAttributeMaxDynamicSharedMemorySize, SMEM_PIPE);
        attr_done = 1;
    }

    k_wprep<<<dim3(32, 4), dim3(32, 32)>>>(w_out);
    k_proj<<<1024, 256>>>(m, mask, lnw, lnb, w1, b1, w2, b2);
    k_gemm1_mma<<<dim3(64, 64), 256, SMEM_PIPE>>>();
    k_gemm2_mma<<<512, 256, SMEM_PIPE>>>(mask, b_out, out);
}